// round 16
// baseline (speedup 1.0000x reference)
#include <cuda_runtime.h>
#include <cuda_bf16.h>
#include <cstdint>

#define BIMG 16
#define AANC 65536
#define GGT  32
#define CAP  8192
#define HBINS 1024
#define HBASE 0x3C00
#define K1BLK 256            // k1 blocks per image (256 sorted anchors each)
#define K3BLK 32             // k3 blocks per image

// ---------------- device scratch (static, zero-init; kernels self-clean) ----------------
__device__ unsigned            gNumPos[BIMG];
__device__ double              gLocSum[BIMG];
__device__ double              gPosBce[BIMG];
__device__ double              gNegSum[BIMG];
__device__ unsigned            gPredCnt[BIMG];
__device__ double              gIouSum;
__device__ unsigned            gIouCnt;
__device__ unsigned long long  gBestGt[BIMG * GGT];   // packed (iou_bits<<32)|(65535-a); 0 = valid floor
__device__ float               gNegP[BIMG * AANC];    // p for negatives, 0 for positives (SORTED anchor order)
__device__ unsigned            gHist[BIMG * HBINS];   // p-prefix histogram
__device__ unsigned            gPrefix[BIMG];
__device__ unsigned            gRem[BIMG];
__device__ unsigned            gCandCnt[BIMG];
__device__ unsigned            gCand[BIMG * CAP];
__device__ unsigned            gImgDone1[BIMG];
__device__ unsigned            gImgDone3[BIMG];
__device__ unsigned            gAllDone;
// anchor spatial sort (image-independent)
__device__ float4              gAnchS[AANC];          // anchors in cell-sorted order
__device__ unsigned            gAIdx[AANC];           // sorted pos -> original index
__device__ unsigned            gInvOrd[AANC];         // original index -> sorted pos
__device__ unsigned            gBlkCnt[64 * 64];      // [cell][blk]
__device__ unsigned            gBlkBase[64 * 64];     // [cell][blk] scatter base
__device__ unsigned            gSortDone;

// ---------------- helpers ----------------
__device__ __forceinline__ float sl1(float d) {
    return d < 1.0f ? 0.5f * d * d : d - 0.5f;
}

__device__ __forceinline__ float loc_loss4(float4 P, float4 M) {
    float dcx = fabsf((P.x + P.z) * 0.5f - (M.x + M.z) * 0.5f);
    float dcy = fabsf((P.y + P.w) * 0.5f - (M.y + M.w) * 0.5f);
    float dw  = fabsf((P.z - P.x) - (M.z - M.x));
    float dh  = fabsf((P.w - P.y) - (M.w - M.y));
    return sl1(dcx) + sl1(dcy) + sl1(dw) + sl1(dh);
}

__device__ __forceinline__ float bce_neg(float p) {       // t=0 BCE, torch clamp
    return fminf(-log1pf(-p), 100.0f);
}

__device__ __forceinline__ int pbin(float p) {            // monotone clamped bin
    int bin = (int)(__float_as_uint(p) >> 16) - HBASE;
    return min(max(bin, 0), HBINS - 1);
}

__device__ __forceinline__ int cellc(float x) {           // clamped 8-grid cell coord
    return min(max(__float2int_rd(x * 8.0f), 0), 7);
}

// inclusive SUFFIX scan over 256 threads (2 barriers, warp shuffles).
__device__ __forceinline__ unsigned suffix_scan_256(unsigned v, unsigned* sW, int t) {
    const int lane = t & 31, w = t >> 5;
    unsigned x = v;
    #pragma unroll
    for (int off = 1; off < 32; off <<= 1) {
        unsigned y = __shfl_down_sync(0xffffffffu, x, off);
        if (lane + off < 32) x += y;
    }
    if (lane == 0) sW[w] = x;
    __syncthreads();
    if (t < 8) {
        unsigned s = sW[t];
        #pragma unroll
        for (int off = 1; off < 8; off <<= 1) {
            unsigned y = __shfl_down_sync(0x000000ffu, s, off);
            if (t + off < 8) s += y;
        }
        sW[t] = s;
    }
    __syncthreads();
    unsigned later = (w < 7) ? sW[w + 1] : 0u;
    return x + later;
}

// ---------------- kA: per-block cell counts + (last block) scan ----------------
__global__ void __launch_bounds__(256) kA_count(const float4* __restrict__ anchors) {
    __shared__ unsigned cnt[64];
    __shared__ unsigned sTot[64], sBase[64];
    __shared__ unsigned sRank;
    const int t = threadIdx.x, blk = blockIdx.x;   // 64 blocks x 1024 anchors
    if (t < 64) cnt[t] = 0u;
    __syncthreads();
    #pragma unroll
    for (int i = 0; i < 4; ++i) {
        float4 an = anchors[blk * 1024 + i * 256 + t];
        int cx = cellc((an.x + an.z) * 0.5f), cy = cellc((an.y + an.w) * 0.5f);
        atomicAdd(&cnt[cy * 8 + cx], 1u);
    }
    __syncthreads();
    if (t < 64) gBlkCnt[t * 64 + blk] = cnt[t];    // plain store: self-cleaning
    __threadfence();
    __syncthreads();
    if (t == 0) sRank = atomicAdd(&gSortDone, 1u);
    __syncthreads();
    if (sRank != 63u) return;
    // ---- last block: exclusive scan (cell-major over blocks, then over cells) ----
    if (t < 64) {
        unsigned run = 0;
        for (int j = 0; j < 64; ++j) {
            gBlkBase[t * 64 + j] = run;
            run += __ldcg(&gBlkCnt[t * 64 + j]);
        }
        sTot[t] = run;
    }
    __syncthreads();
    if (t == 0) {
        unsigned run = 0;
        for (int c = 0; c < 64; ++c) { sBase[c] = run; run += sTot[c]; }
        gSortDone = 0u;                            // self-clean for next replay
    }
    __syncthreads();
    if (t < 64) {
        unsigned b0 = sBase[t];
        for (int j = 0; j < 64; ++j) gBlkBase[t * 64 + j] += b0;
    }
}

// ---------------- kB: scatter anchors into cell-sorted order ----------------
__global__ void __launch_bounds__(256) kB_scatter(const float4* __restrict__ anchors) {
    __shared__ unsigned off[64];
    const int t = threadIdx.x, blk = blockIdx.x;
    if (t < 64) off[t] = __ldcg(&gBlkBase[t * 64 + blk]);
    __syncthreads();
    #pragma unroll
    for (int i = 0; i < 4; ++i) {
        int a = blk * 1024 + i * 256 + t;
        float4 an = anchors[a];
        int cx = cellc((an.x + an.z) * 0.5f), cy = cellc((an.y + an.w) * 0.5f);
        unsigned pos = atomicAdd(&off[cy * 8 + cx], 1u);
        gAnchS[pos] = an;
        gAIdx[pos] = (unsigned)a;
        gInvOrd[a] = pos;
    }
}

// ---------------- K1: warp-uniform cell-pruned IoU pass + fused per-image tail ----------------
__global__ void __launch_bounds__(256) k1_main(
    const float4* __restrict__ bbox,      // [B,A] float4
    const float*  __restrict__ conf,      // [B,A]
    const float4* __restrict__ anchors,   // [A] float4 (original order)
    const float4* __restrict__ gt)        // [B,G] float4
{
    __shared__ float4 sGt[GGT];
    __shared__ float  sAreaG[GGT];
    __shared__ unsigned long long sBest[GGT];
    __shared__ unsigned sCell[64];        // 8x8 grid -> gt bitmask (exact superset)
    __shared__ unsigned sW[9];
    __shared__ int      sIdx[GGT];
    __shared__ unsigned sRank, sNpAdd, sK;
    __shared__ double   sLocAdd, sBceAdd;

    const int b = blockIdx.y;
    const int t = threadIdx.x;
    const int p0 = blockIdx.x * 256 + t;  // sorted anchor position
    const int lane = t & 31;

    if (t < GGT) {
        float4 g = gt[b * GGT + t];
        sGt[t] = g;
        sAreaG[t] = (g.z - g.x) * (g.w - g.y);
        sBest[t] = 65535ULL;              // iou=0, anchor a=0
    }
    __syncthreads();
    // cell -> gt mask: gt touches cell iff clamped cell range covers it
    if (t < 64) {
        const int cx = t & 7, cy = t >> 3;
        unsigned m = 0u;
        #pragma unroll
        for (int g = 0; g < GGT; ++g) {
            float4 G = sGt[g];
            bool hit = (cellc(G.x) <= cx) && (cx <= cellc(G.z)) &&
                       (cellc(G.y) <= cy) && (cy <= cellc(G.w));
            m |= hit ? (1u << g) : 0u;
        }
        sCell[t] = m;
    }
    __syncthreads();

    const float4 an = gAnchS[p0];                 // coalesced (sorted)
    const unsigned aidx = gAIdx[p0];              // original anchor index
    const float areaA = (an.z - an.x) * (an.w - an.y);

    // per-anchor exact candidate mask (box cells), then WARP-UNIFORM union
    unsigned ms = 0u;
    {
        const int cx0 = cellc(an.x), cx1 = cellc(an.z);
        const int cy0 = cellc(an.y), cy1 = cellc(an.w);
        for (int cy = cy0; cy <= cy1; ++cy)
            for (int cx = cx0; cx <= cx1; ++cx)
                ms |= sCell[cy * 8 + cx];
    }
    unsigned mw = __reduce_or_sync(0xffffffffu, ms);   // warp-uniform superset

    // uniform candidate loop (g not in mask => inter == 0 exactly => no effect)
    float bi = 0.0f, bu = 1.0f;
    int   besti = 0;
    while (mw) {
        const int g = __ffs(mw) - 1;
        mw &= mw - 1u;
        const float4 G = sGt[g];
        float w = fmaxf(fminf(an.z, G.z) - fmaxf(an.x, G.x), 0.0f);
        float h = fmaxf(fminf(an.w, G.w) - fmaxf(an.y, G.y), 0.0f);
        float inter = w * h;
        float ueps = ((areaA + sAreaG[g]) - inter) + 1e-6f;   // ref eval order
        bool better = inter * bu > bi * ueps;                  // cross-mult argmax
        bi    = better ? inter : bi;
        bu    = better ? ueps  : bu;
        besti = better ? g     : besti;
        const float sf = __uint_as_float(((const unsigned*)&sBest[g])[1]);
        if (inter > 0.0f && inter >= sf * ueps) {              // rare prefilter pass
            float iou = inter / ueps;
            atomicMax(&sBest[g],
                      ((unsigned long long)__float_as_uint(iou) << 32) |
                      (unsigned long long)(65535u - aidx));
        }
    }

    const float bestf = bi / bu;              // identical expr to reference
    const bool pos0 = bestf > 0.5f;
    const float p = conf[b * AANC + aidx];    // scattered gather (original order)
    gNegP[b * AANC + p0] = pos0 ? 0.0f : p;   // coalesced store (sorted order)
    if (!pos0) atomicAdd(&gHist[(b << 10) + pbin(p)], 1u);
    if (pos0) {
        float4 M = sGt[besti];
        float4 P = bbox[b * AANC + aidx];
        atomicAdd(&gLocSum[b], (double)loc_loss4(P, M));
        atomicAdd(&gPosBce[b], (double)fminf(-logf(p), 100.0f));
    }

    unsigned mPred = __ballot_sync(0xffffffffu, p > 0.5f);
    unsigned mPos  = __ballot_sync(0xffffffffu, pos0);
    if (lane == 0) {
        if (mPred) atomicAdd(&gPredCnt[b], (unsigned)__popc(mPred));
        if (mPos)  atomicAdd(&gNumPos[b],  (unsigned)__popc(mPos));
    }
    if (b == BIMG - 1) {
        float iouv = bestf > 0.0f ? bestf : 0.0f;
        #pragma unroll
        for (int o = 16; o; o >>= 1) iouv += __shfl_down_sync(0xffffffffu, iouv, o);
        unsigned mI = __ballot_sync(0xffffffffu, bestf > 0.0f);
        if (lane == 0) {
            if (iouv != 0.0f) atomicAdd(&gIouSum, (double)iouv);
            if (mI) atomicAdd(&gIouCnt, (unsigned)__popc(mI));
        }
    }

    __syncthreads();
    if (t < GGT) atomicMax(&gBestGt[b * GGT + t], sBest[t]);
    __threadfence();
    __syncthreads();
    if (t == 0) sRank = atomicAdd(&gImgDone1[b], 1u);
    __syncthreads();
    if (sRank != K1BLK - 1) return;

    // ======== last block of image b: fixup + threshold select + self-clean ========
    if (t == 0) { sNpAdd = 0u; sLocAdd = 0.0; sBceAdd = 0.0; }
    __syncthreads();

    if (t < GGT) {
        unsigned long long pk = gBestGt[b * GGT + t];
        int aa = 65535 - (int)(pk & 0xffffffffu);
        sIdx[t] = aa;
        __syncwarp();
        bool owner = true;
        for (int j = 0; j < t; ++j)
            if (sIdx[j] == aa) owner = false;
        if (owner) {
            float4 an1 = anchors[aa];
            float areaA1 = (an1.z - an1.x) * (an1.w - an1.y);
            float bestv = -1.0f;
            float4 Mb = sGt[0];
            for (int j = 0; j < GGT; ++j) {
                float4 G = sGt[j];
                float w = fmaxf(fminf(an1.z, G.z) - fmaxf(an1.x, G.x), 0.0f);
                float h = fmaxf(fminf(an1.w, G.w) - fmaxf(an1.y, G.y), 0.0f);
                float inter = w * h;
                float iou = inter / (((areaA1 + sAreaG[j]) - inter) + 1e-6f);
                if (iou > bestv) { bestv = iou; Mb = G; }
            }
            if (bestv <= 0.5f) {   // not already positive in main pass
                float p1 = conf[b * AANC + aa];
                atomicAdd(&sNpAdd, 1u);
                atomicAdd(&sBceAdd, (double)fminf(-logf(p1), 100.0f));
                float4 P = bbox[b * AANC + aa];
                atomicAdd(&sLocAdd, (double)loc_loss4(P, Mb));
                atomicSub(&gHist[(b << 10) + pbin(p1)], 1u);
                gNegP[b * AANC + __ldcg(&gInvOrd[aa])] = 0.0f;  // sorted position
            }
        }
    }
    __syncthreads();

    // self-clean for next graph replay
    if (t < GGT) gBestGt[b * GGT + t] = 0ULL;
    if (t == 32) gImgDone1[b] = 0u;

    if (t == 0) {
        unsigned np = __ldcg(&gNumPos[b]) + sNpAdd;
        if (sNpAdd) {
            gNumPos[b] = np;
            gLocSum[b] = __ldcg(&gLocSum[b]) + sLocAdd;
            gPosBce[b] = __ldcg(&gPosBce[b]) + sBceAdd;
        }
        sK = min(3u * np, (unsigned)AANC - np);
        if (sK == 0u) { gPrefix[b] = 0xFFFFFFFFu; gRem[b] = 0u; }
    }
    __syncthreads();

    // load hist chunk (L2), then zero for next replay
    uint4 hv = __ldcg(&((const uint4*)&gHist[b << 10])[t]);
    ((uint4*)&gHist[b << 10])[t] = make_uint4(0u, 0u, 0u, 0u);

    const unsigned kk = sK;
    if (kk == 0u) return;

    const unsigned v = hv.x + hv.y + hv.z + hv.w;
    const unsigned St = suffix_scan_256(v, sW, t);
    const unsigned Snext = St - v;
    if (St >= kk && Snext < kk) {
        unsigned acc = Snext;
        unsigned vb[4] = {hv.x, hv.y, hv.z, hv.w};
        unsigned pre = 0xFFFFFFFFu, rem = 0u;
        for (int j = 3; j >= 0; --j) {
            unsigned cc = vb[j];
            if (acc + cc >= kk) { pre = (unsigned)(t * 4 + j) + HBASE; rem = kk - acc; break; }
            acc += cc;
        }
        gPrefix[b] = pre; gRem[b] = rem;
    }
}

// ---------------- K3: collect + (last block/image) select + (last block) finalize ----------------
__global__ void __launch_bounds__(256) k3_rest(float* __restrict__ out) {
    const int b = blockIdx.y;
    const int t = threadIdx.x;
    const unsigned th = gPrefix[b];      // threshold prefix; 0xFFFFFFFF = k==0
    const float4* __restrict__ nb = (const float4*)&gNegP[b * AANC];
    const int v4base = (blockIdx.x * 256 + t) * 2;     // 8 elems/thread
    __shared__ float sWsum[8];
    __shared__ unsigned sW[9];

    float4 v[2];
    #pragma unroll
    for (int j = 0; j < 2; ++j) v[j] = nb[v4base + j];

    float fsum = 0.0f;
    #pragma unroll
    for (int j = 0; j < 2; ++j) {
        float vv[4] = {v[j].x, v[j].y, v[j].z, v[j].w};
        #pragma unroll
        for (int c = 0; c < 4; ++c) {
            unsigned u = __float_as_uint(vv[c]);
            unsigned hb = u >> 16;
            if (hb > th) fsum += bce_neg(vv[c]);         // lazy BCE, rare
            else if (hb == th) {
                unsigned idx = atomicAdd(&gCandCnt[b], 1u);
                if (idx < CAP) gCand[b * CAP + idx] = u;
            }
        }
    }
    #pragma unroll
    for (int o = 16; o; o >>= 1) fsum += __shfl_down_sync(0xffffffffu, fsum, o);
    if ((t & 31) == 0) sWsum[t >> 5] = fsum;
    __syncthreads();
    if (t == 0) {
        float bs = 0.0f;
        #pragma unroll
        for (int w = 0; w < 8; ++w) bs += sWsum[w];
        if (bs != 0.0f) atomicAdd(&gNegSum[b], (double)bs);
    }

    __threadfence();
    __shared__ unsigned sRank;
    if (t == 0) sRank = atomicAdd(&gImgDone3[b], 1u);
    __syncthreads();
    if (sRank != K3BLK - 1) return;

    if (th != 0xFFFFFFFFu) {
        __shared__ unsigned hist[256];
        __shared__ unsigned sSel, sRem;
        __shared__ double   wsum[8];

        const unsigned n = min(__ldcg(&gCandCnt[b]), (unsigned)CAP);
        unsigned rem = gRem[b];
        const unsigned* __restrict__ cd = &gCand[b * CAP];

        // round 1: bits [8:16)
        hist[t] = 0u; __syncthreads();
        for (unsigned i = t; i < n; i += 256) atomicAdd(&hist[(__ldcg(&cd[i]) >> 8) & 255u], 1u);
        __syncthreads();
        {
            unsigned hvv = hist[t];
            unsigned St = suffix_scan_256(hvv, sW, t);
            unsigned Snext = St - hvv;
            if (St >= rem && Snext < rem) { sSel = (unsigned)t; sRem = rem - Snext; }
        }
        __syncthreads();
        const unsigned sel1 = sSel;
        rem = sRem;
        __syncthreads();

        // round 2: bits [0:8)
        hist[t] = 0u; __syncthreads();
        for (unsigned i = t; i < n; i += 256) {
            unsigned u = __ldcg(&cd[i]);
            if (((u >> 8) & 255u) == sel1) atomicAdd(&hist[u & 255u], 1u);
        }
        __syncthreads();
        {
            unsigned hvv = hist[t];
            unsigned St = suffix_scan_256(hvv, sW, t);
            unsigned Snext = St - hvv;
            if (St >= rem && Snext < rem) { sSel = (unsigned)t; sRem = rem - Snext; }
        }
        __syncthreads();

        const unsigned vt = (th << 16) | (sel1 << 8) | sSel;   // exact k-th p bits
        const unsigned remf = sRem;

        float ssum = 0.0f;
        for (unsigned i = t; i < n; i += 256) {
            unsigned u = __ldcg(&cd[i]);
            if (u > vt) ssum += bce_neg(__uint_as_float(u));
        }
        #pragma unroll
        for (int o = 16; o; o >>= 1) ssum += __shfl_down_sync(0xffffffffu, ssum, o);
        if ((t & 31) == 0) wsum[t >> 5] = (double)ssum;
        __syncthreads();
        if (t == 0) {
            double s = 0.0;
            for (int w = 0; w < 8; ++w) s += wsum[w];
            s += (double)remf * (double)bce_neg(__uint_as_float(vt));
            atomicAdd(&gNegSum[b], s);
        }
        __syncthreads();
    }

    // self-clean per-image state for next replay
    if (t == 0) { gCandCnt[b] = 0u; gImgDone3[b] = 0u; }

    // ---- last image to finish runs finalize (parallel over 16 lanes) ----
    __threadfence();
    __shared__ unsigned sAll;
    if (t == 0) sAll = atomicAdd(&gAllDone, 1u);
    __syncthreads();
    if (sAll == BIMG - 1 && t < 32) {
        unsigned np = 0;
        double loc = 0.0, confl = 0.0, cpen = 0.0;
        if (t < BIMG) {
            np    = __ldcg(&gNumPos[t]);
            loc   = __ldcg(&gLocSum[t]);
            confl = __ldcg(&gNegSum[t]) + __ldcg(&gPosBce[t]);
            float diff = fabsf((float)((int)__ldcg(&gPredCnt[t]) - GGT));
            float pen = (diff <= 3.0f) ? diff * 0.2f
                                       : 0.6f + 0.2f * logf(fmaxf(diff - 2.0f, 1.0f));
            cpen = (double)pen;
            gNumPos[t] = 0u; gLocSum[t] = 0.0; gPosBce[t] = 0.0;
            gNegSum[t] = 0.0; gPredCnt[t] = 0u;
        }
        #pragma unroll
        for (int o = 8; o; o >>= 1) {
            np    += __shfl_down_sync(0xffffffffu, np, o);
            loc   += __shfl_down_sync(0xffffffffu, loc, o);
            confl += __shfl_down_sync(0xffffffffu, confl, o);
            cpen  += __shfl_down_sync(0xffffffffu, cpen, o);
        }
        if (t == 0) {
            float npos = (float)(np > 0u ? np : 1u);
            float tl = (float)loc / npos;
            float tc = (float)confl / npos;
            float tcnt = (float)cpen / (float)BIMG;
            unsigned icnt = __ldcg(&gIouCnt);
            double isum = __ldcg(&gIouSum);
            float mean = (icnt > 0u) ? (float)(isum / (double)icnt) : 0.1f;
            float iq = fminf(fmaxf(1.0f - mean, 0.1f), 0.9f);
            out[0] = (1.0f + iq) * tl + 1.0f * tc + 0.2f * tcnt;
            out[1] = tc;
            out[2] = tl;
            out[3] = tcnt;
            out[4] = mean;
            gIouSum = 0.0; gIouCnt = 0u; gAllDone = 0u;
        }
    }
}

// ---------------- launch ----------------
extern "C" void kernel_launch(void* const* d_in, const int* in_sizes, int n_in,
                              void* d_out, int out_size) {
    const float4* bbox    = (const float4*)d_in[0];   // [16,65536,4]
    const float*  conf    = (const float*)d_in[1];    // [16,65536]
    const float4* anchors = (const float4*)d_in[2];   // [65536,4]
    const float4* gt      = (const float4*)d_in[3];   // [16,32,4]
    float* out = (float*)d_out;

    kA_count<<<64, 256>>>(anchors);
    kB_scatter<<<64, 256>>>(anchors);
    k1_main<<<dim3(K1BLK, BIMG), 256>>>(bbox, conf, anchors, gt);
    k3_rest<<<dim3(K3BLK, BIMG), 256>>>(out);
}

// round 17
// speedup vs baseline: 1.4001x; 1.4001x over previous
#include <cuda_runtime.h>
#include <cuda_bf16.h>
#include <cstdint>

#define BIMG 16
#define AANC 65536
#define GGT  32
#define CAP  8192
#define HBINS 1024
#define HBASE 0x3C00
#define K1BLK 64            // k1 blocks per image
#define K3BLK 16            // k3 blocks per image (16 elems/thread)

// ---------------- device scratch (static, zero-init; kernels self-clean) ----------------
__device__ unsigned            gNumPos[BIMG];
__device__ double              gLocSum[BIMG];
__device__ double              gPosBce[BIMG];
__device__ double              gNegSum[BIMG];
__device__ unsigned            gPredCnt[BIMG];
__device__ double              gIouSum;
__device__ unsigned            gIouCnt;
__device__ unsigned long long  gBestGt[BIMG * GGT];      // packed (iou_bits<<32)|(65535-a); 0 = valid floor
__device__ float               gNegP[BIMG * AANC];       // 4MB: p for negatives, 0 for positives
__device__ unsigned            gHist[BIMG * HBINS];      // 64KB: p-prefix histogram
__device__ unsigned            gPrefix[BIMG];            // threshold 16-bit prefix (or 0xFFFFFFFF)
__device__ unsigned            gRem[BIMG];               // count needed from boundary bin
__device__ unsigned            gCandCnt[BIMG];
__device__ unsigned            gCand[BIMG * CAP];
__device__ unsigned            gImgDone1[BIMG];          // k1 per-image block counter
__device__ unsigned            gImgDone3[BIMG];          // k3 per-image block counter
__device__ unsigned            gAllDone;

// ---------------- helpers ----------------
__device__ __forceinline__ float sl1(float d) {
    return d < 1.0f ? 0.5f * d * d : d - 0.5f;
}

__device__ __forceinline__ float loc_loss4(float4 P, float4 M) {
    float dcx = fabsf((P.x + P.z) * 0.5f - (M.x + M.z) * 0.5f);
    float dcy = fabsf((P.y + P.w) * 0.5f - (M.y + M.w) * 0.5f);
    float dw  = fabsf((P.z - P.x) - (M.z - M.x));
    float dh  = fabsf((P.w - P.y) - (M.w - M.y));
    return sl1(dcx) + sl1(dcy) + sl1(dw) + sl1(dh);
}

__device__ __forceinline__ float bce_neg(float p) {       // t=0 BCE, torch clamp
    return fminf(-log1pf(-p), 100.0f);
}

__device__ __forceinline__ int pbin(float p) {            // monotone clamped bin
    int bin = (int)(__float_as_uint(p) >> 16) - HBASE;
    return min(max(bin, 0), HBINS - 1);
}

// ---------------- K1: branchless IoU pass (in-loop rare updates) + fused tail ----------------
__global__ void __launch_bounds__(256) k1_main(
    const float4* __restrict__ bbox,      // [B,A] float4
    const float*  __restrict__ conf,      // [B,A]
    const float4* __restrict__ anchors,   // [A] float4
    const float4* __restrict__ gt)        // [B,G] float4
{
    __shared__ float4 sGt[GGT];
    __shared__ float  sAreaG[GGT];
    __shared__ unsigned long long sBest[GGT];
    __shared__ unsigned sCsum[256];
    __shared__ int      sIdx[GGT];
    __shared__ unsigned sRank, sNpAdd, sK;
    __shared__ double   sLocAdd, sBceAdd;

    const int b = blockIdx.y;
    const int t = threadIdx.x;
    const int a0 = blockIdx.x * 1024 + t;      // anchors a0 + 256*k, k=0..3
    const int lane = t & 31;

    if (t < GGT) {
        float4 g = gt[b * GGT + t];
        sGt[t] = g;
        sAreaG[t] = (g.z - g.x) * (g.w - g.y);
        sBest[t] = 65535ULL;
    }
    __syncthreads();

    float4 an[4];
    float  areaA[4], bi[4], bu[4], pconf[4];
    int    besti[4];
    #pragma unroll
    for (int k = 0; k < 4; ++k) {
        an[k] = anchors[a0 + 256 * k];
        areaA[k] = (an[k].z - an[k].x) * (an[k].w - an[k].y);
        bi[k] = 0.0f; bu[k] = 1.0f; besti[k] = 0;
        pconf[k] = conf[b * AANC + a0 + 256 * k];   // hoisted: latency hidden by g-loop
    }

    // ---- hot loop: branchless argmax + in-loop rare per-gt update ----
    #pragma unroll 8
    for (int g = 0; g < GGT; ++g) {
        const float4 G = sGt[g];
        const float areaG = sAreaG[g];
        const float sf = __uint_as_float(((const unsigned*)&sBest[g])[1]);
        float inter[4], ueps[4];
        bool pf[4];
        bool anypf = false;
        #pragma unroll
        for (int k = 0; k < 4; ++k) {
            float w = fmaxf(fminf(an[k].z, G.z) - fmaxf(an[k].x, G.x), 0.0f);
            float h = fmaxf(fminf(an[k].w, G.w) - fmaxf(an[k].y, G.y), 0.0f);
            inter[k] = w * h;
            ueps[k] = ((areaA[k] + areaG) - inter[k]) + 1e-6f;   // ref eval order
            // branchless argmax via cross-multiplication (all terms >= 0)
            bool better = inter[k] * bu[k] > bi[k] * ueps[k];
            bi[k]    = better ? inter[k] : bi[k];
            bu[k]    = better ? ueps[k]  : bu[k];
            besti[k] = better ? g        : besti[k];
            // per-gt best-anchor prefilter (exact div deferred to rare region)
            pf[k] = (inter[k] > 0.0f) && (inter[k] >= sf * ueps[k]);
            anypf |= pf[k];
        }
        if (anypf) {            // rare; in-loop atomic keeps sf rising -> self-pruning
            #pragma unroll
            for (int k = 0; k < 4; ++k) {
                if (pf[k]) {
                    float iou = inter[k] / ueps[k];
                    atomicMax(&sBest[g],
                              ((unsigned long long)__float_as_uint(iou) << 32) |
                              (unsigned long long)(65535u - (unsigned)(a0 + 256 * k)));
                }
            }
        }
    }

    unsigned npred = 0, npos = 0, ioucnt = 0;
    float iouv = 0.0f;
    #pragma unroll
    for (int k = 0; k < 4; ++k) {
        const int a = a0 + 256 * k;
        const float bestf = bi[k] / bu[k];          // identical expr to reference
        const bool pos0 = bestf > 0.5f;
        const float p = pconf[k];
        gNegP[b * AANC + a] = pos0 ? 0.0f : p;      // monotone proxy for neg BCE
        if (!pos0) atomicAdd(&gHist[(b << 10) + pbin(p)], 1u);
        npred += (p > 0.5f);
        npos  += pos0;
        if (pos0) {
            float4 M = sGt[besti[k]];
            float4 P = bbox[b * AANC + a];
            atomicAdd(&gLocSum[b], (double)loc_loss4(P, M));
            atomicAdd(&gPosBce[b], (double)fminf(-logf(p), 100.0f));
        }
        if (b == BIMG - 1 && bestf > 0.0f) { iouv += bestf; ioucnt++; }
    }

    npred = __reduce_add_sync(0xffffffffu, npred);
    npos  = __reduce_add_sync(0xffffffffu, npos);
    if (lane == 0) {
        if (npred) atomicAdd(&gPredCnt[b], npred);
        if (npos)  atomicAdd(&gNumPos[b], npos);
    }
    if (b == BIMG - 1) {
        #pragma unroll
        for (int o = 16; o; o >>= 1) iouv += __shfl_down_sync(0xffffffffu, iouv, o);
        ioucnt = __reduce_add_sync(0xffffffffu, ioucnt);
        if (lane == 0) {
            if (iouv != 0.0f) atomicAdd(&gIouSum, (double)iouv);
            if (ioucnt) atomicAdd(&gIouCnt, ioucnt);
        }
    }

    __syncthreads();
    if (t < GGT) atomicMax(&gBestGt[b * GGT + t], sBest[t]);
    __threadfence();
    __syncthreads();
    if (t == 0) sRank = atomicAdd(&gImgDone1[b], 1u);
    __syncthreads();
    if (sRank != K1BLK - 1) return;

    // ======== last block of image b: fixup + threshold select + state self-clean ========
    if (t == 0) { sNpAdd = 0u; sLocAdd = 0.0; sBceAdd = 0.0; }
    __syncthreads();

    if (t < GGT) {
        unsigned long long pk = gBestGt[b * GGT + t];
        int a = 65535 - (int)(pk & 0xffffffffu);
        sIdx[t] = a;
        __syncwarp();
        bool owner = true;
        for (int j = 0; j < t; ++j)
            if (sIdx[j] == a) owner = false;
        if (owner) {
            float4 an1 = anchors[a];
            float areaA1 = (an1.z - an1.x) * (an1.w - an1.y);
            float bestv = -1.0f;
            float4 Mb = sGt[0];
            for (int j = 0; j < GGT; ++j) {
                float4 G = sGt[j];
                float w = fmaxf(fminf(an1.z, G.z) - fmaxf(an1.x, G.x), 0.0f);
                float h = fmaxf(fminf(an1.w, G.w) - fmaxf(an1.y, G.y), 0.0f);
                float inter = w * h;
                float iou = inter / (((areaA1 + sAreaG[j]) - inter) + 1e-6f);
                if (iou > bestv) { bestv = iou; Mb = G; }
            }
            if (bestv <= 0.5f) {   // not already positive in main pass
                float p = conf[b * AANC + a];
                atomicAdd(&sNpAdd, 1u);
                atomicAdd(&sBceAdd, (double)fminf(-logf(p), 100.0f));
                float4 P = bbox[b * AANC + a];
                atomicAdd(&sLocAdd, (double)loc_loss4(P, Mb));
                atomicSub(&gHist[(b << 10) + pbin(p)], 1u);
                gNegP[b * AANC + a] = 0.0f;
            }
        }
    }
    __syncthreads();

    // self-clean for next graph replay (after fixup consumed gBestGt)
    if (t < GGT) gBestGt[b * GGT + t] = 0ULL;
    if (t == 32) gImgDone1[b] = 0u;

    if (t == 0) {
        unsigned np = gNumPos[b] + sNpAdd;
        if (sNpAdd) {
            gNumPos[b] = np;
            gLocSum[b] += sLocAdd;
            gPosBce[b] += sBceAdd;
        }
        sK = min(3u * np, (unsigned)AANC - np);
        if (sK == 0u) { gPrefix[b] = 0xFFFFFFFFu; gRem[b] = 0u; }
    }
    __syncthreads();

    // load hist chunk, then zero it for the next replay
    uint4 hv = __ldcg(&((const uint4*)&gHist[b << 10])[t]);
    ((uint4*)&gHist[b << 10])[t] = make_uint4(0u, 0u, 0u, 0u);

    const unsigned kk = sK;
    if (kk == 0u) return;

    // 256 threads, 4 bins each; suffix scan over chunk sums
    sCsum[t] = hv.x + hv.y + hv.z + hv.w;
    __syncthreads();
    #pragma unroll
    for (int off = 1; off < 256; off <<= 1) {
        unsigned v = sCsum[t] + ((t + off < 256) ? sCsum[t + off] : 0u);
        __syncthreads();
        sCsum[t] = v;
        __syncthreads();
    }
    unsigned St = sCsum[t];
    unsigned Snext = (t < 255) ? sCsum[t + 1] : 0u;
    if (St >= kk && Snext < kk) {
        unsigned acc = Snext;
        unsigned vb[4] = {hv.x, hv.y, hv.z, hv.w};
        unsigned pre = 0xFFFFFFFFu, rem = 0u;
        for (int j = 3; j >= 0; --j) {
            unsigned cc = vb[j];
            if (acc + cc >= kk) { pre = (unsigned)(t * 4 + j) + HBASE; rem = kk - acc; break; }
            acc += cc;
        }
        gPrefix[b] = pre; gRem[b] = rem;
    }
}

// ---------------- K3: collect (16 elems, 4x LDG.128) + select + finalize ----------------
__global__ void __launch_bounds__(256) k3_rest(float* __restrict__ out) {
    const int b = blockIdx.y;
    const int t = threadIdx.x;
    const unsigned th = gPrefix[b];      // threshold prefix; 0xFFFFFFFF = k==0
    const float4* __restrict__ nb = (const float4*)&gNegP[b * AANC];
    const int v4base = (blockIdx.x * 256 + t) * 4;     // 16 elems/thread
    __shared__ float sWsum[8];

    float4 v[4];
    #pragma unroll
    for (int j = 0; j < 4; ++j) v[j] = nb[v4base + j];  // 4 independent LDG.128

    float fsum = 0.0f;                                   // float accum: no FP64 chain
    #pragma unroll
    for (int j = 0; j < 4; ++j) {
        float vv[4] = {v[j].x, v[j].y, v[j].z, v[j].w};
        #pragma unroll
        for (int c = 0; c < 4; ++c) {
            unsigned u = __float_as_uint(vv[c]);
            unsigned hb = u >> 16;
            if (hb > th) fsum += bce_neg(vv[c]);         // lazy BCE, rare
            else if (hb == th) {
                unsigned idx = atomicAdd(&gCandCnt[b], 1u);
                if (idx < CAP) gCand[b * CAP + idx] = u;
            }
        }
    }
    // two-level reduce: warp shuffle -> shared -> ONE global double atomic per block
    #pragma unroll
    for (int o = 16; o; o >>= 1) fsum += __shfl_down_sync(0xffffffffu, fsum, o);
    if ((t & 31) == 0) sWsum[t >> 5] = fsum;
    __syncthreads();
    if (t == 0) {
        float bs = 0.0f;
        #pragma unroll
        for (int w = 0; w < 8; ++w) bs += sWsum[w];
        if (bs != 0.0f) atomicAdd(&gNegSum[b], (double)bs);
    }

    // ---- last collect block of this image runs the boundary select ----
    __threadfence();
    __shared__ unsigned sRank;
    if (t == 0) sRank = atomicAdd(&gImgDone3[b], 1u);
    __syncthreads();
    if (sRank != K3BLK - 1) return;

    if (th != 0xFFFFFFFFu) {
        __shared__ unsigned hist[256];
        __shared__ unsigned scan[256];
        __shared__ unsigned sSel, sRem;
        __shared__ double   wsum[8];

        const unsigned n = min(__ldcg(&gCandCnt[b]), (unsigned)CAP);
        unsigned rem = gRem[b];
        const unsigned* __restrict__ cd = &gCand[b * CAP];

        // round 1: bits [8:16)
        hist[t] = 0u; __syncthreads();
        for (unsigned i = t; i < n; i += 256) atomicAdd(&hist[(__ldcg(&cd[i]) >> 8) & 255u], 1u);
        __syncthreads();
        scan[t] = hist[t];
        __syncthreads();
        #pragma unroll
        for (int off = 1; off < 256; off <<= 1) {
            unsigned vs = scan[t] + ((t + off < 256) ? scan[t + off] : 0u);
            __syncthreads();
            scan[t] = vs;
            __syncthreads();
        }
        {
            unsigned St = scan[t];
            unsigned Snext = (t < 255) ? scan[t + 1] : 0u;
            if (St >= rem && Snext < rem) { sSel = (unsigned)t; sRem = rem - Snext; }
        }
        __syncthreads();
        const unsigned sel1 = sSel;
        rem = sRem;
        __syncthreads();

        // round 2: bits [0:8)
        hist[t] = 0u; __syncthreads();
        for (unsigned i = t; i < n; i += 256) {
            unsigned u = __ldcg(&cd[i]);
            if (((u >> 8) & 255u) == sel1) atomicAdd(&hist[u & 255u], 1u);
        }
        __syncthreads();
        scan[t] = hist[t];
        __syncthreads();
        #pragma unroll
        for (int off = 1; off < 256; off <<= 1) {
            unsigned vs = scan[t] + ((t + off < 256) ? scan[t + off] : 0u);
            __syncthreads();
            scan[t] = vs;
            __syncthreads();
        }
        {
            unsigned St = scan[t];
            unsigned Snext = (t < 255) ? scan[t + 1] : 0u;
            if (St >= rem && Snext < rem) { sSel = (unsigned)t; sRem = rem - Snext; }
        }
        __syncthreads();

        const unsigned vt = (th << 16) | (sel1 << 8) | sSel;   // exact k-th p bits
        const unsigned remf = sRem;

        float ssum = 0.0f;
        for (unsigned i = t; i < n; i += 256) {
            unsigned u = __ldcg(&cd[i]);
            if (u > vt) ssum += bce_neg(__uint_as_float(u));
        }
        #pragma unroll
        for (int o = 16; o; o >>= 1) ssum += __shfl_down_sync(0xffffffffu, ssum, o);
        if ((t & 31) == 0) wsum[t >> 5] = (double)ssum;
        __syncthreads();
        if (t == 0) {
            double s = 0.0;
            for (int w = 0; w < 8; ++w) s += wsum[w];
            s += (double)remf * (double)bce_neg(__uint_as_float(vt));
            atomicAdd(&gNegSum[b], s);
        }
        __syncthreads();
    }

    // self-clean per-image state for next replay
    if (t == 0) { gCandCnt[b] = 0u; gImgDone3[b] = 0u; }

    // ---- last image to finish runs finalize (parallel over 16 lanes) ----
    __threadfence();
    __shared__ unsigned sAll;
    if (t == 0) sAll = atomicAdd(&gAllDone, 1u);
    __syncthreads();
    if (sAll == BIMG - 1 && t < 32) {
        unsigned np = 0;
        double loc = 0.0, confl = 0.0, cpen = 0.0;
        if (t < BIMG) {
            np    = gNumPos[t];
            loc   = gLocSum[t];
            confl = gNegSum[t] + gPosBce[t];
            float diff = fabsf((float)((int)gPredCnt[t] - GGT));
            float pen = (diff <= 3.0f) ? diff * 0.2f
                                       : 0.6f + 0.2f * logf(fmaxf(diff - 2.0f, 1.0f));
            cpen = (double)pen;
            // self-clean accumulators for next replay
            gNumPos[t] = 0u; gLocSum[t] = 0.0; gPosBce[t] = 0.0;
            gNegSum[t] = 0.0; gPredCnt[t] = 0u;
        }
        #pragma unroll
        for (int o = 8; o; o >>= 1) {
            np    += __shfl_down_sync(0xffffffffu, np, o);
            loc   += __shfl_down_sync(0xffffffffu, loc, o);
            confl += __shfl_down_sync(0xffffffffu, confl, o);
            cpen  += __shfl_down_sync(0xffffffffu, cpen, o);
        }
        if (t == 0) {
            float npos = (float)(np > 0u ? np : 1u);
            float tl = (float)loc / npos;
            float tc = (float)confl / npos;
            float tcnt = (float)cpen / (float)BIMG;
            float mean = (gIouCnt > 0u) ? (float)(gIouSum / (double)gIouCnt) : 0.1f;
            float iq = fminf(fmaxf(1.0f - mean, 0.1f), 0.9f);
            out[0] = (1.0f + iq) * tl + 1.0f * tc + 0.2f * tcnt;
            out[1] = tc;
            out[2] = tl;
            out[3] = tcnt;
            out[4] = mean;
            gIouSum = 0.0; gIouCnt = 0u; gAllDone = 0u;
        }
    }
}

// ---------------- launch ----------------
extern "C" void kernel_launch(void* const* d_in, const int* in_sizes, int n_in,
                              void* d_out, int out_size) {
    const float4* bbox    = (const float4*)d_in[0];   // [16,65536,4]
    const float*  conf    = (const float*)d_in[1];    // [16,65536]
    const float4* anchors = (const float4*)d_in[2];   // [65536,4]
    const float4* gt      = (const float4*)d_in[3];   // [16,32,4]
    float* out = (float*)d_out;

    k1_main<<<dim3(K1BLK, BIMG), 256>>>(bbox, conf, anchors, gt);
    k3_rest<<<dim3(K3BLK, BIMG), 256>>>(out);
}